// round 12
// baseline (speedup 1.0000x reference)
#include <cuda_runtime.h>
#include <cuda_fp16.h>
#include <math_constants.h>

#define VOCAB    100000
#define RAND_DIM 100
#define WAE      50
#define CLS      4
#define VDIM     100
#define NPATH    16384
#define PLEN     50
#define HDIM     150     // RAND_DIM + WAE
#define PADT     160     // table row pitch in halves: 320 B = 20 uint4, 10 sectors
#define NBLK     (NPATH / 8)

typedef unsigned long long ull;

// Fused gather table: row v = [fp16 E_td[v][0:100] | fp16 G[v][0:50] | pad 10]
// where G = E_wae @ W_enc (tensor-core precompute).
__device__ __align__(16) __half g_T[(size_t)VOCAB * PADT];   // 32 MB
__device__ float  g_max[HDIM];
__device__ int    g_done;

// ---------------------------------------------------------------------------
__device__ __forceinline__ __half2 asH2(unsigned u) {
    return *reinterpret_cast<__half2*>(&u);
}
__device__ __forceinline__ void atomicMaxF(float* addr, float v) {
    if (v >= 0.f) atomicMax((int*)addr, __float_as_int(v));
    else          atomicMin((unsigned int*)addr, __float_as_uint(v));
}
__device__ __forceinline__ ull packh(float a, float b, float c, float d) {
    __half2 h0 = __floats2half2_rn(a, b);
    __half2 h1 = __floats2half2_rn(c, d);
    unsigned lo = *reinterpret_cast<unsigned*>(&h0);
    unsigned hi = *reinterpret_cast<unsigned*>(&h1);
    return (ull)lo | ((ull)hi << 32);
}
__device__ __forceinline__ unsigned packh2u(float a, float b) {
    __half2 h = __floats2half2_rn(a, b);
    return *reinterpret_cast<unsigned*>(&h);
}
__device__ __forceinline__ uint4 ldcg4(const uint4* p) {
    uint4 v;
    asm volatile("ld.global.cg.v4.u32 {%0,%1,%2,%3}, [%4];"
                 : "=r"(v.x), "=r"(v.y), "=r"(v.z), "=r"(v.w) : "l"(p));
    return v;
}

// ---------------------------------------------------------------------------
// Kernel 1 (fused prep): per block of 128 vocab rows,
//   (a) stream-convert E_td rows -> table cols 0..99 (fp16)
//   (b) G = E_wae @ W_enc via mma.sync m16n8k16 -> table cols 100..149
// The convert stream overlaps the MMA/A-load latency; E_td and E_wae DRAM
// reads overlap chip-wide; one launch instead of two.
// Block = 256 threads = 8 warps; warp owns 16 vocab rows.
// B (W_enc) staged in smem [n][k] fp16, pitch 120 halves.
// ---------------------------------------------------------------------------
__device__ __forceinline__ unsigned loadA_h2(const float* E, int r, int c) {
    if (r < VOCAB && c < VDIM) {
        float2 v = *reinterpret_cast<const float2*>(E + (size_t)r * VDIM + c);
        return packh2u(v.x, v.y);
    }
    return 0u;
}

__global__ void __launch_bounds__(256)
wae_prep_kernel(const float* __restrict__ E_td,
                const float* __restrict__ E_wae,
                const float* __restrict__ W_enc) {
    __shared__ __half sB[56 * 120];   // [n][k], pitch 120 halves
    int tid = threadIdx.x, w = tid >> 5, lane = tid & 31;
    int row0 = blockIdx.x * 128;

    if (blockIdx.x == 0) {
        if (tid < HDIM) g_max[tid] = -CUDART_INF_F;
        if (tid == 0)   g_done = 0;
    }

    // stage W_enc
    for (int i = tid; i < 56 * 112; i += 256) {
        int n = i / 112, k = i % 112;
        float v = (n < WAE && k < VDIM) ? __ldg(&W_enc[k * WAE + n]) : 0.f;
        sB[n * 120 + k] = __float2half(v);
    }

    // stream-convert this block's 128 E_td rows -> table cols 0..99
    {
        const float4* A = (const float4*)E_td;   // 25 float4 per row
        ull* T = (ull*)g_T;                      // 40 ull per row
        for (int i = tid; i < 128 * 25; i += 256) {
            int r = row0 + i / 25, j = i % 25;
            if (r < VOCAB) {
                float4 v = __ldcs(&A[(size_t)r * 25 + j]);
                T[(size_t)r * 40 + j] = packh(v.x, v.y, v.z, v.w);
            }
        }
    }
    __syncthreads();

    // tensor-core GEMM: 16 rows per warp
    int r0 = row0 + w * 16 + (lane >> 2);   // fragment row (plus +8 variant)
    int cb = (lane & 3) * 2;                // fragment col-pair base

    float acc[7][4];
    #pragma unroll
    for (int nt = 0; nt < 7; nt++)
        acc[nt][0] = acc[nt][1] = acc[nt][2] = acc[nt][3] = 0.f;

    #pragma unroll
    for (int ks = 0; ks < 7; ks++) {
        int c0 = ks * 16 + cb;
        unsigned a0 = loadA_h2(E_wae, r0,     c0);
        unsigned a1 = loadA_h2(E_wae, r0 + 8, c0);
        unsigned a2 = loadA_h2(E_wae, r0,     c0 + 8);
        unsigned a3 = loadA_h2(E_wae, r0 + 8, c0 + 8);
        int k0 = ks * 16 + cb;
        #pragma unroll
        for (int nt = 0; nt < 7; nt++) {
            int n = nt * 8 + (lane >> 2);
            unsigned b0 = *reinterpret_cast<unsigned*>(&sB[n * 120 + k0]);
            unsigned b1 = *reinterpret_cast<unsigned*>(&sB[n * 120 + k0 + 8]);
            asm volatile(
                "mma.sync.aligned.m16n8k16.row.col.f32.f16.f16.f32 "
                "{%0,%1,%2,%3}, {%4,%5,%6,%7}, {%8,%9}, {%0,%1,%2,%3};\n"
                : "+f"(acc[nt][0]), "+f"(acc[nt][1]),
                  "+f"(acc[nt][2]), "+f"(acc[nt][3])
                : "r"(a0), "r"(a1), "r"(a2), "r"(a3), "r"(b0), "r"(b1));
        }
    }

    #pragma unroll
    for (int nt = 0; nt < 7; nt++) {
        int col = nt * 8 + cb;                       // even; pair (col, col+1)
        if (col < WAE) {
            unsigned lo = packh2u(acc[nt][0], acc[nt][1]);
            unsigned hi = packh2u(acc[nt][2], acc[nt][3]);
            if (r0 < VOCAB)
                *reinterpret_cast<unsigned*>(
                    &g_T[(size_t)r0 * PADT + RAND_DIM + col]) = lo;
            if (r0 + 8 < VOCAB)
                *reinterpret_cast<unsigned*>(
                    &g_T[(size_t)(r0 + 8) * PADT + RAND_DIM + col]) = hi;
        }
    }
}

// ---------------------------------------------------------------------------
// Kernel 2: gather + activations + max-pool + fused finalize (R11 body).
// One warp per path, lanes 0..18 own 16B chunks (dims 8l..8l+7) of the
// 300B row (pitch 320B, 10 sectors, <=3 cachelines per load).
// ---------------------------------------------------------------------------
__global__ void __launch_bounds__(256, 8)
path_gather_kernel(const int*   __restrict__ x,
                   const float* __restrict__ b_enc,
                   const float* __restrict__ w_out,
                   const float* __restrict__ b_out,
                   const int*   __restrict__ y,
                   float* __restrict__ out, int out_size) {
    __shared__ float smax[HDIM];
    __shared__ int   s_last;
    int tid = threadIdx.x;
    if (tid < HDIM) smax[tid] = -CUDART_INF_F;
    __syncthreads();

    int w = tid >> 5, lane = tid & 31;
    int p = blockIdx.x * 8 + w;
    const int* xp = x + (size_t)p * PLEN;

    int tA = xp[lane];
    int tB = (lane < PLEN - 32) ? xp[32 + lane] : 0;

    bool act = lane < 19;                         // chunks covering dims 0..151
    const uint4* T4 = (const uint4*)g_T + lane;   // per-lane chunk base, 20/row

    float2 a0 = {0.f, 0.f}, a1 = {0.f, 0.f}, a2 = {0.f, 0.f}, a3 = {0.f, 0.f};

    #pragma unroll
    for (int t = 0; t < 48; t += 4) {
        int k0 = (t     < 32) ? __shfl_sync(0xffffffffu, tA, t)     : __shfl_sync(0xffffffffu, tB, t - 32);
        int k1 = (t + 1 < 32) ? __shfl_sync(0xffffffffu, tA, t + 1) : __shfl_sync(0xffffffffu, tB, t - 31);
        int k2 = (t + 2 < 32) ? __shfl_sync(0xffffffffu, tA, t + 2) : __shfl_sync(0xffffffffu, tB, t - 30);
        int k3 = (t + 3 < 32) ? __shfl_sync(0xffffffffu, tA, t + 3) : __shfl_sync(0xffffffffu, tB, t - 29);
        if (act) {
            uint4 v0 = ldcg4(T4 + (size_t)k0 * 20);
            uint4 v1 = ldcg4(T4 + (size_t)k1 * 20);
            uint4 v2 = ldcg4(T4 + (size_t)k2 * 20);
            uint4 v3 = ldcg4(T4 + (size_t)k3 * 20);
            __half2 s0 = __hadd2(__hadd2(asH2(v0.x), asH2(v1.x)), __hadd2(asH2(v2.x), asH2(v3.x)));
            __half2 s1 = __hadd2(__hadd2(asH2(v0.y), asH2(v1.y)), __hadd2(asH2(v2.y), asH2(v3.y)));
            __half2 s2 = __hadd2(__hadd2(asH2(v0.z), asH2(v1.z)), __hadd2(asH2(v2.z), asH2(v3.z)));
            __half2 s3 = __hadd2(__hadd2(asH2(v0.w), asH2(v1.w)), __hadd2(asH2(v2.w), asH2(v3.w)));
            float2 f;
            f = __half22float2(s0); a0.x += f.x; a0.y += f.y;
            f = __half22float2(s1); a1.x += f.x; a1.y += f.y;
            f = __half22float2(s2); a2.x += f.x; a2.y += f.y;
            f = __half22float2(s3); a3.x += f.x; a3.y += f.y;
        }
    }
    {   // tail: tokens 48, 49
        int k0 = __shfl_sync(0xffffffffu, tB, 16);
        int k1 = __shfl_sync(0xffffffffu, tB, 17);
        if (act) {
            uint4 v0 = ldcg4(T4 + (size_t)k0 * 20);
            uint4 v1 = ldcg4(T4 + (size_t)k1 * 20);
            __half2 s0 = __hadd2(asH2(v0.x), asH2(v1.x));
            __half2 s1 = __hadd2(asH2(v0.y), asH2(v1.y));
            __half2 s2 = __hadd2(asH2(v0.z), asH2(v1.z));
            __half2 s3 = __hadd2(asH2(v0.w), asH2(v1.w));
            float2 f;
            f = __half22float2(s0); a0.x += f.x; a0.y += f.y;
            f = __half22float2(s1); a1.x += f.x; a1.y += f.y;
            f = __half22float2(s2); a2.x += f.x; a2.y += f.y;
            f = __half22float2(s3); a3.x += f.x; a3.y += f.y;
        }
    }

    if (act) {
        float f[8] = {a0.x, a0.y, a1.x, a1.y, a2.x, a2.y, a3.x, a3.y};
        int d0 = lane * 8;
        #pragma unroll
        for (int j = 0; j < 8; j++) {
            int d = d0 + j;
            if (d < RAND_DIM) {                       // path_random: leaky_relu
                float v = f[j];
                v = (v > 0.f) ? v : 0.01f * v;
                atomicMaxF(&smax[d], v);
            } else if (d < HDIM) {                    // G dims: relu(sum + b)
                float v = fmaxf(f[j] + __ldg(&b_enc[d - RAND_DIM]), 0.f);
                atomicMaxF(&smax[d], v);
            }
        }
    }
    __syncthreads();

    if (tid < HDIM) atomicMaxF(&g_max[tid], smax[tid]);

    // ---- fused finalize: last block computes softmax + loss ----
    __threadfence();
    if (tid == 0) s_last = (atomicAdd(&g_done, 1) == NBLK - 1);
    __syncthreads();
    if (!s_last || w != 0) return;

    float part[CLS] = {0.f, 0.f, 0.f, 0.f};
    for (int d = lane; d < HDIM; d += 32) {
        float m = __ldcg(&g_max[d]);
        #pragma unroll
        for (int c = 0; c < CLS; c++)
            part[c] = fmaf(w_out[c * HDIM + d], m, part[c]);
    }
    #pragma unroll
    for (int off = 16; off > 0; off >>= 1) {
        #pragma unroll
        for (int c = 0; c < CLS; c++)
            part[c] += __shfl_down_sync(0xffffffffu, part[c], off);
    }
    if (lane == 0) {
        float logits[CLS], prob[CLS];
        float mx = -CUDART_INF_F;
        #pragma unroll
        for (int c = 0; c < CLS; c++) {
            logits[c] = part[c] + b_out[c];
            mx = fmaxf(mx, logits[c]);
        }
        float s = 0.f;
        #pragma unroll
        for (int c = 0; c < CLS; c++) { prob[c] = expf(logits[c] - mx); s += prob[c]; }
        #pragma unroll
        for (int c = 0; c < CLS; c++) prob[c] /= s;

        int label = 0, best = y[0];
        #pragma unroll
        for (int c = 1; c < CLS; c++) if (y[c] > best) { best = y[c]; label = c; }

        float mx2 = prob[0];
        #pragma unroll
        for (int c = 1; c < CLS; c++) mx2 = fmaxf(mx2, prob[c]);
        float s2 = 0.f;
        #pragma unroll
        for (int c = 0; c < CLS; c++) s2 += expf(prob[c] - mx2);
        float loss = -(prob[label] - (mx2 + logf(s2)));

        for (int c = 0; c < CLS && c < out_size; c++) out[c] = prob[c];
        if (out_size > CLS) out[CLS] = loss;
    }
}

// ---------------------------------------------------------------------------
extern "C" void kernel_launch(void* const* d_in, const int* in_sizes, int n_in,
                              void* d_out, int out_size) {
    const int*   x     = (const int*)  d_in[0];
    const int*   y     = (const int*)  d_in[1];
    const float* E_td  = (const float*)d_in[2];
    const float* E_wae = (const float*)d_in[3];
    const float* W_enc = (const float*)d_in[4];
    const float* b_enc = (const float*)d_in[5];
    const float* w_out = (const float*)d_in[6];
    const float* b_out = (const float*)d_in[7];
    float* out = (float*)d_out;

    wae_prep_kernel<<<(VOCAB + 127) / 128, 256>>>(E_td, E_wae, W_enc);
    path_gather_kernel<<<NBLK, 256>>>(x, b_enc, w_out, b_out, y,
                                      out, out_size);
}

// round 13
// speedup vs baseline: 1.1421x; 1.1421x over previous
#include <cuda_runtime.h>
#include <cuda_fp16.h>
#include <math_constants.h>

#define VOCAB    100000
#define RAND_DIM 100
#define WAE      50
#define CLS      4
#define VDIM     100
#define NPATH    16384
#define PLEN     50
#define HDIM     150     // RAND_DIM + WAE
#define PADT     160     // table row pitch in halves: 320 B = 20 uint4
#define NBLK     (NPATH / 8)
#define GEMM_BLKS ((VOCAB + 127) / 128)   // 782
#define CONV_BLKS 1184

typedef unsigned long long ull;

// Fused gather table: row v = [fp16 E_td[v][0:100] | fp16 G[v][0:50] | pad 10]
__device__ __align__(16) __half g_T[(size_t)VOCAB * PADT];   // 32 MB
__device__ float  g_max[HDIM];
__device__ int    g_done;

// ---------------------------------------------------------------------------
__device__ __forceinline__ __half2 asH2(unsigned u) {
    return *reinterpret_cast<__half2*>(&u);
}
__device__ __forceinline__ void atomicMaxF(float* addr, float v) {
    if (v >= 0.f) atomicMax((int*)addr, __float_as_int(v));
    else          atomicMin((unsigned int*)addr, __float_as_uint(v));
}
__device__ __forceinline__ ull packh(float a, float b, float c, float d) {
    __half2 h0 = __floats2half2_rn(a, b);
    __half2 h1 = __floats2half2_rn(c, d);
    unsigned lo = *reinterpret_cast<unsigned*>(&h0);
    unsigned hi = *reinterpret_cast<unsigned*>(&h1);
    return (ull)lo | ((ull)hi << 32);
}
__device__ __forceinline__ unsigned packh2u(float a, float b) {
    __half2 h = __floats2half2_rn(a, b);
    return *reinterpret_cast<unsigned*>(&h);
}
__device__ __forceinline__ uint4 ldcg4(const uint4* p) {
    uint4 v;
    asm volatile("ld.global.cg.v4.u32 {%0,%1,%2,%3}, [%4];"
                 : "=r"(v.x), "=r"(v.y), "=r"(v.z), "=r"(v.w) : "l"(p));
    return v;
}
__device__ __forceinline__ unsigned loadA_h2(const float* E, int r, int c) {
    if (r < VOCAB && c < VDIM) {
        float2 v = *reinterpret_cast<const float2*>(E + (size_t)r * VDIM + c);
        return packh2u(v.x, v.y);
    }
    return 0u;
}

// ---------------------------------------------------------------------------
// Kernel 1 (fat prep): blocks [0, GEMM_BLKS) run the tensor-core GEMM
// (G = E_wae @ W_enc -> table cols 100..149); blocks [GEMM_BLKS, +CONV_BLKS)
// stream-convert E_td -> table cols 0..99. The two roles run CONCURRENTLY
// across SMs (no intra-block serialization, unlike R12's fusion).
// ---------------------------------------------------------------------------
__global__ void __launch_bounds__(256)
wae_prep_fat_kernel(const float* __restrict__ E_td,
                    const float* __restrict__ E_wae,
                    const float* __restrict__ W_enc) {
    int tid = threadIdx.x;

    if (blockIdx.x == 0) {
        if (tid < HDIM) g_max[tid] = -CUDART_INF_F;
        if (tid == 0)   g_done = 0;
    }

    if (blockIdx.x < GEMM_BLKS) {
        // ---------------- GEMM role (R11's wae_gemm_kernel) ----------------
        __shared__ __half sB[56 * 120];   // [n][k], pitch 120 halves
        int w = tid >> 5, lane = tid & 31;
        int row0 = blockIdx.x * 128;

        for (int i = tid; i < 56 * 112; i += 256) {
            int n = i / 112, k = i % 112;
            float v = (n < WAE && k < VDIM) ? __ldg(&W_enc[k * WAE + n]) : 0.f;
            sB[n * 120 + k] = __float2half(v);
        }
        __syncthreads();

        int r0 = row0 + w * 16 + (lane >> 2);
        int cb = (lane & 3) * 2;

        float acc[7][4];
        #pragma unroll
        for (int nt = 0; nt < 7; nt++)
            acc[nt][0] = acc[nt][1] = acc[nt][2] = acc[nt][3] = 0.f;

        #pragma unroll
        for (int ks = 0; ks < 7; ks++) {
            int c0 = ks * 16 + cb;
            unsigned a0 = loadA_h2(E_wae, r0,     c0);
            unsigned a1 = loadA_h2(E_wae, r0 + 8, c0);
            unsigned a2 = loadA_h2(E_wae, r0,     c0 + 8);
            unsigned a3 = loadA_h2(E_wae, r0 + 8, c0 + 8);
            int k0 = ks * 16 + cb;
            #pragma unroll
            for (int nt = 0; nt < 7; nt++) {
                int n = nt * 8 + (lane >> 2);
                unsigned b0 = *reinterpret_cast<unsigned*>(&sB[n * 120 + k0]);
                unsigned b1 = *reinterpret_cast<unsigned*>(&sB[n * 120 + k0 + 8]);
                asm volatile(
                    "mma.sync.aligned.m16n8k16.row.col.f32.f16.f16.f32 "
                    "{%0,%1,%2,%3}, {%4,%5,%6,%7}, {%8,%9}, {%0,%1,%2,%3};\n"
                    : "+f"(acc[nt][0]), "+f"(acc[nt][1]),
                      "+f"(acc[nt][2]), "+f"(acc[nt][3])
                    : "r"(a0), "r"(a1), "r"(a2), "r"(a3), "r"(b0), "r"(b1));
            }
        }

        #pragma unroll
        for (int nt = 0; nt < 7; nt++) {
            int col = nt * 8 + cb;
            if (col < WAE) {
                unsigned lo = packh2u(acc[nt][0], acc[nt][1]);
                unsigned hi = packh2u(acc[nt][2], acc[nt][3]);
                if (r0 < VOCAB)
                    *reinterpret_cast<unsigned*>(
                        &g_T[(size_t)r0 * PADT + RAND_DIM + col]) = lo;
                if (r0 + 8 < VOCAB)
                    *reinterpret_cast<unsigned*>(
                        &g_T[(size_t)(r0 + 8) * PADT + RAND_DIM + col]) = hi;
            }
        }
    } else {
        // ---------------- convert role (R11's convert_td_kernel) -----------
        const float4* A = (const float4*)E_td;   // 25 float4 per row
        ull* T = (ull*)g_T;                      // 40 ull per row
        const size_t N = (size_t)VOCAB * 25;
        size_t stride = (size_t)CONV_BLKS * 256;
        size_t i0 = (size_t)(blockIdx.x - GEMM_BLKS) * 256 + tid;
        for (size_t i = i0; i < N; i += stride) {
            float4 v = __ldcs(&A[i]);
            size_t row = i / 25, j = i % 25;
            T[row * 40 + j] = packh(v.x, v.y, v.z, v.w);
        }
    }
}

// ---------------------------------------------------------------------------
// Kernel 2: gather + activations + max-pool + fused finalize (R12's
// measured-37.3us body, unchanged).
// ---------------------------------------------------------------------------
__global__ void __launch_bounds__(256, 8)
path_gather_kernel(const int*   __restrict__ x,
                   const float* __restrict__ b_enc,
                   const float* __restrict__ w_out,
                   const float* __restrict__ b_out,
                   const int*   __restrict__ y,
                   float* __restrict__ out, int out_size) {
    __shared__ float smax[HDIM];
    __shared__ int   s_last;
    int tid = threadIdx.x;
    if (tid < HDIM) smax[tid] = -CUDART_INF_F;
    __syncthreads();

    int w = tid >> 5, lane = tid & 31;
    int p = blockIdx.x * 8 + w;
    const int* xp = x + (size_t)p * PLEN;

    int tA = xp[lane];
    int tB = (lane < PLEN - 32) ? xp[32 + lane] : 0;

    bool act = lane < 19;                         // chunks covering dims 0..151
    const uint4* T4 = (const uint4*)g_T + lane;   // per-lane chunk base, 20/row

    float2 a0 = {0.f, 0.f}, a1 = {0.f, 0.f}, a2 = {0.f, 0.f}, a3 = {0.f, 0.f};

    #pragma unroll
    for (int t = 0; t < 48; t += 4) {
        int k0 = (t     < 32) ? __shfl_sync(0xffffffffu, tA, t)     : __shfl_sync(0xffffffffu, tB, t - 32);
        int k1 = (t + 1 < 32) ? __shfl_sync(0xffffffffu, tA, t + 1) : __shfl_sync(0xffffffffu, tB, t - 31);
        int k2 = (t + 2 < 32) ? __shfl_sync(0xffffffffu, tA, t + 2) : __shfl_sync(0xffffffffu, tB, t - 30);
        int k3 = (t + 3 < 32) ? __shfl_sync(0xffffffffu, tA, t + 3) : __shfl_sync(0xffffffffu, tB, t - 29);
        if (act) {
            uint4 v0 = ldcg4(T4 + (size_t)k0 * 20);
            uint4 v1 = ldcg4(T4 + (size_t)k1 * 20);
            uint4 v2 = ldcg4(T4 + (size_t)k2 * 20);
            uint4 v3 = ldcg4(T4 + (size_t)k3 * 20);
            __half2 s0 = __hadd2(__hadd2(asH2(v0.x), asH2(v1.x)), __hadd2(asH2(v2.x), asH2(v3.x)));
            __half2 s1 = __hadd2(__hadd2(asH2(v0.y), asH2(v1.y)), __hadd2(asH2(v2.y), asH2(v3.y)));
            __half2 s2 = __hadd2(__hadd2(asH2(v0.z), asH2(v1.z)), __hadd2(asH2(v2.z), asH2(v3.z)));
            __half2 s3 = __hadd2(__hadd2(asH2(v0.w), asH2(v1.w)), __hadd2(asH2(v2.w), asH2(v3.w)));
            float2 f;
            f = __half22float2(s0); a0.x += f.x; a0.y += f.y;
            f = __half22float2(s1); a1.x += f.x; a1.y += f.y;
            f = __half22float2(s2); a2.x += f.x; a2.y += f.y;
            f = __half22float2(s3); a3.x += f.x; a3.y += f.y;
        }
    }
    {   // tail: tokens 48, 49
        int k0 = __shfl_sync(0xffffffffu, tB, 16);
        int k1 = __shfl_sync(0xffffffffu, tB, 17);
        if (act) {
            uint4 v0 = ldcg4(T4 + (size_t)k0 * 20);
            uint4 v1 = ldcg4(T4 + (size_t)k1 * 20);
            __half2 s0 = __hadd2(asH2(v0.x), asH2(v1.x));
            __half2 s1 = __hadd2(asH2(v0.y), asH2(v1.y));
            __half2 s2 = __hadd2(asH2(v0.z), asH2(v1.z));
            __half2 s3 = __hadd2(asH2(v0.w), asH2(v1.w));
            float2 f;
            f = __half22float2(s0); a0.x += f.x; a0.y += f.y;
            f = __half22float2(s1); a1.x += f.x; a1.y += f.y;
            f = __half22float2(s2); a2.x += f.x; a2.y += f.y;
            f = __half22float2(s3); a3.x += f.x; a3.y += f.y;
        }
    }

    if (act) {
        float f[8] = {a0.x, a0.y, a1.x, a1.y, a2.x, a2.y, a3.x, a3.y};
        int d0 = lane * 8;
        #pragma unroll
        for (int j = 0; j < 8; j++) {
            int d = d0 + j;
            if (d < RAND_DIM) {                       // path_random: leaky_relu
                float v = f[j];
                v = (v > 0.f) ? v : 0.01f * v;
                atomicMaxF(&smax[d], v);
            } else if (d < HDIM) {                    // G dims: relu(sum + b)
                float v = fmaxf(f[j] + __ldg(&b_enc[d - RAND_DIM]), 0.f);
                atomicMaxF(&smax[d], v);
            }
        }
    }
    __syncthreads();

    if (tid < HDIM) atomicMaxF(&g_max[tid], smax[tid]);

    // ---- fused finalize: last block computes softmax + loss ----
    __threadfence();
    if (tid == 0) s_last = (atomicAdd(&g_done, 1) == NBLK - 1);
    __syncthreads();
    if (!s_last || w != 0) return;

    float part[CLS] = {0.f, 0.f, 0.f, 0.f};
    for (int d = lane; d < HDIM; d += 32) {
        float m = __ldcg(&g_max[d]);
        #pragma unroll
        for (int c = 0; c < CLS; c++)
            part[c] = fmaf(w_out[c * HDIM + d], m, part[c]);
    }
    #pragma unroll
    for (int off = 16; off > 0; off >>= 1) {
        #pragma unroll
        for (int c = 0; c < CLS; c++)
            part[c] += __shfl_down_sync(0xffffffffu, part[c], off);
    }
    if (lane == 0) {
        float logits[CLS], prob[CLS];
        float mx = -CUDART_INF_F;
        #pragma unroll
        for (int c = 0; c < CLS; c++) {
            logits[c] = part[c] + b_out[c];
            mx = fmaxf(mx, logits[c]);
        }
        float s = 0.f;
        #pragma unroll
        for (int c = 0; c < CLS; c++) { prob[c] = expf(logits[c] - mx); s += prob[c]; }
        #pragma unroll
        for (int c = 0; c < CLS; c++) prob[c] /= s;

        int label = 0, best = y[0];
        #pragma unroll
        for (int c = 1; c < CLS; c++) if (y[c] > best) { best = y[c]; label = c; }

        float mx2 = prob[0];
        #pragma unroll
        for (int c = 1; c < CLS; c++) mx2 = fmaxf(mx2, prob[c]);
        float s2 = 0.f;
        #pragma unroll
        for (int c = 0; c < CLS; c++) s2 += expf(prob[c] - mx2);
        float loss = -(prob[label] - (mx2 + logf(s2)));

        for (int c = 0; c < CLS && c < out_size; c++) out[c] = prob[c];
        if (out_size > CLS) out[CLS] = loss;
    }
}

// ---------------------------------------------------------------------------
extern "C" void kernel_launch(void* const* d_in, const int* in_sizes, int n_in,
                              void* d_out, int out_size) {
    const int*   x     = (const int*)  d_in[0];
    const int*   y     = (const int*)  d_in[1];
    const float* E_td  = (const float*)d_in[2];
    const float* E_wae = (const float*)d_in[3];
    const float* W_enc = (const float*)d_in[4];
    const float* b_enc = (const float*)d_in[5];
    const float* w_out = (const float*)d_in[6];
    const float* b_out = (const float*)d_in[7];
    float* out = (float*)d_out;

    wae_prep_fat_kernel<<<GEMM_BLKS + CONV_BLKS, 256>>>(E_td, E_wae, W_enc);
    path_gather_kernel<<<NBLK, 256>>>(x, b_enc, w_out, b_out, y,
                                      out, out_size);
}